// round 11
// baseline (speedup 1.0000x reference)
#include <cuda_runtime.h>
#include <cuda_bf16.h>

#define NJ 24
#define EPSF 1e-6f
#define TPB 128

typedef unsigned long long ull;

__device__ __forceinline__ ull f2_fma(ull a, ull b, ull c) {
    ull d; asm("fma.rn.f32x2 %0, %1, %2, %3;" : "=l"(d) : "l"(a), "l"(b), "l"(c)); return d;
}
__device__ __forceinline__ ull f2_mul(ull a, ull b) {
    ull d; asm("mul.rn.f32x2 %0, %1, %2;" : "=l"(d) : "l"(a), "l"(b)); return d;
}
__device__ __forceinline__ ull f2_add(ull a, ull b) {
    ull d; asm("add.rn.f32x2 %0, %1, %2;" : "=l"(d) : "l"(a), "l"(b)); return d;
}
__device__ __forceinline__ ull f2_pack(float lo, float hi) {
    ull d;
    asm("mov.b64 %0, {%1, %2};" : "=l"(d) : "r"(__float_as_uint(lo)), "r"(__float_as_uint(hi)));
    return d;
}
__device__ __forceinline__ void f2_unpack(ull a, float& lo, float& hi) {
    unsigned int l, h;
    asm("mov.b64 {%0, %1}, %2;" : "=r"(l), "=r"(h) : "l"(a));
    lo = __uint_as_float(l); hi = __uint_as_float(h);
}
__device__ __forceinline__ float sqrt_ap(float x) {
    float r; asm("sqrt.approx.f32 %0, %1;" : "=f"(r) : "f"(x)); return r;
}
__device__ __forceinline__ float rcp_ap(float x) {
    float r; asm("rcp.approx.f32 %0, %1;" : "=f"(r) : "f"(x)); return r;
}

// Shared A-consts per joint, duplicated {v,v} pairs, stride 28:
//  0 G00 1 G11 2 G22 3 2G01 4 2G02 5 2G12 6 bn0 7 bn1 8 bn2 9 cn
// 10 M00 11 M11 12 M22 13 2M01 14 2M02 15 2M12 16 bP0 17 bP1 18 bP2 19 cP
// 20 lL0 21 lL1 22 lL2 23 eL 24 tr0 25 tr1 26 tr2 27 pad
// Shared B-consts per joint, stride 12: 0..8 = R row-major, 9..11 pad.

__global__ __launch_bounds__(TPB)
void shCaster_kernel(const float* __restrict__ xyz,
                     const float* __restrict__ vdir,
                     const float* __restrict__ transforms,
                     const float* __restrict__ sh_feats,
                     const float* __restrict__ locs,
                     float* __restrict__ out,
                     int half, int n)
{
    __shared__ __align__(16) ull SA[NJ * 28];
    __shared__ __align__(16) ull SB[NJ * 12];
    __shared__ ull SW[NJ * TPB];

    // ---- per-joint constant precompute (quadratic forms in x) ----
    if (threadIdx.x < NJ) {
        const int j = threadIdx.x;
        const float C0c = 0.28209479177387814f;
        const float C1c = 0.4886025119029199f;
        const float Bc  = 1.0925484305920792f;
        const float Cc  = 0.31539156525252005f;
        const float Dc  = 0.5462742152960396f;

        float R[3][3], trv[3], e[3];
        #pragma unroll
        for (int r = 0; r < 3; ++r) {
            #pragma unroll
            for (int c = 0; c < 3; ++c) R[r][c] = transforms[j * 16 + r * 4 + c];
            trv[r] = transforms[j * 16 + r * 4 + 3];
        }
        #pragma unroll
        for (int i = 0; i < 3; ++i) e[i] = locs[j * 3 + i] - trv[i];

        float f[9];
        #pragma unroll
        for (int k = 0; k < 9; ++k) f[k] = sh_feats[j * 9 + k];

        float a0p = C0c * f[0] + 0.5f - Cc * f[6];
        float aL[3] = { -C1c * f[3], -C1c * f[1], C1c * f[2] };  // coeff on (dx,dy,dz)
        float a4 = Bc * f[4], a5 = -Bc * f[5], a7 = -Bc * f[7], a8 = Dc * f[8];
        float b6 = 3.0f * Cc * f[6];

        float H[3][3];
        H[0][0] = a8;  H[1][1] = -a8;  H[2][2] = b6;
        H[0][1] = H[1][0] = 0.5f * a4;
        H[1][2] = H[2][1] = 0.5f * a5;
        H[0][2] = H[2][0] = 0.5f * a7;

        float G[3][3], HR[3][3], M2[3][3], he[3];
        #pragma unroll
        for (int a = 0; a < 3; ++a)
            #pragma unroll
            for (int b = 0; b < 3; ++b) {
                float s = 0.f;
                #pragma unroll
                for (int i = 0; i < 3; ++i) s += R[i][a] * R[i][b];
                G[a][b] = s;
            }
        #pragma unroll
        for (int i = 0; i < 3; ++i) {
            #pragma unroll
            for (int c = 0; c < 3; ++c) {
                float s = 0.f;
                #pragma unroll
                for (int k = 0; k < 3; ++k) s += H[i][k] * R[k][c];
                HR[i][c] = s;
            }
            float s2v = 0.f;
            #pragma unroll
            for (int k = 0; k < 3; ++k) s2v += H[i][k] * e[k];
            he[i] = s2v;
        }
        #pragma unroll
        for (int a = 0; a < 3; ++a)
            #pragma unroll
            for (int b = 0; b < 3; ++b) {
                float s = 0.f;
                #pragma unroll
                for (int i = 0; i < 3; ++i) s += R[i][a] * HR[i][b];
                M2[a][b] = s;
            }

        float bn[3], bQ[3], lL[3];
        #pragma unroll
        for (int a = 0; a < 3; ++a) {
            bn[a] = -2.f * (R[0][a] * e[0] + R[1][a] * e[1] + R[2][a] * e[2]);
            bQ[a] = -2.f * (he[0] * R[0][a] + he[1] * R[1][a] + he[2] * R[2][a]);
            lL[a] = -(aL[0] * R[0][a] + aL[1] * R[1][a] + aL[2] * R[2][a]);
        }
        float cn = e[0]*e[0] + e[1]*e[1] + e[2]*e[2];
        float cQ = e[0]*he[0] + e[1]*he[1] + e[2]*he[2];
        float eL = aL[0]*e[0] + aL[1]*e[1] + aL[2]*e[2];

        float av[28];
        av[0] = G[0][0]; av[1] = G[1][1]; av[2] = G[2][2];
        av[3] = 2.f*G[0][1]; av[4] = 2.f*G[0][2]; av[5] = 2.f*G[1][2];
        av[6] = bn[0]; av[7] = bn[1]; av[8] = bn[2]; av[9] = cn;
        av[10] = a0p*G[0][0] + M2[0][0];
        av[11] = a0p*G[1][1] + M2[1][1];
        av[12] = a0p*G[2][2] + M2[2][2];
        av[13] = 2.f*(a0p*G[0][1] + M2[0][1]);
        av[14] = 2.f*(a0p*G[0][2] + M2[0][2]);
        av[15] = 2.f*(a0p*G[1][2] + M2[1][2]);
        av[16] = a0p*bn[0] + bQ[0];
        av[17] = a0p*bn[1] + bQ[1];
        av[18] = a0p*bn[2] + bQ[2];
        av[19] = a0p*cn + cQ;
        av[20] = lL[0]; av[21] = lL[1]; av[22] = lL[2]; av[23] = eL;
        av[24] = trv[0]; av[25] = trv[1]; av[26] = trv[2]; av[27] = 0.f;

        #pragma unroll
        for (int k = 0; k < 28; ++k) {
            unsigned int b = __float_as_uint(av[k]);
            SA[j * 28 + k] = ((ull)b << 32) | b;
        }
        #pragma unroll
        for (int k = 0; k < 9; ++k) {
            unsigned int b = __float_as_uint(R[k / 3][k % 3]);
            SB[j * 12 + k] = ((ull)b << 32) | b;
        }
        SB[j * 12 + 9] = 0; SB[j * 12 + 10] = 0; SB[j * 12 + 11] = 0;
    }
    __syncthreads();

    int t = blockIdx.x * TPB + threadIdx.x;
    if (t >= half) return;
    int i0 = t, i1 = t + half;

    const ull x2 = f2_pack(__ldg(&xyz[3 * i0]),     __ldg(&xyz[3 * i1]));
    const ull y2 = f2_pack(__ldg(&xyz[3 * i0 + 1]), __ldg(&xyz[3 * i1 + 1]));
    const ull z2 = f2_pack(__ldg(&xyz[3 * i0 + 2]), __ldg(&xyz[3 * i1 + 2]));

    const ull xx2 = f2_mul(x2, x2);
    const ull yy2 = f2_mul(y2, y2);
    const ull zz2 = f2_mul(z2, z2);
    const ull xy2 = f2_mul(x2, y2);
    const ull xz2 = f2_mul(x2, z2);
    const ull yz2 = f2_mul(y2, z2);

    const ull NEG1 = f2_pack(-1.f, -1.f);

    ull wsum2 = 0ull;
    ull wt0 = 0ull, wt1 = 0ull, wt2 = 0ull;   // Sum w * tr

    // ---- Loop A: weights ----
#pragma unroll 4
    for (int j = 0; j < NJ; ++j) {
        const ulonglong2* C = reinterpret_cast<const ulonglong2*>(SA + j * 28);
        const ulonglong2 A0 = C[0],  A1 = C[1],  A2 = C[2],  A3 = C[3],  A4 = C[4];
        const ulonglong2 A5 = C[5],  A6 = C[6],  A7 = C[7],  A8 = C[8],  A9 = C[9];
        const ulonglong2 A10 = C[10], A11 = C[11], A12 = C[12], A13 = C[13];

        // n2(x) = xGx + bn x + cn
        ull n2 = f2_fma(A0.x, xx2, f2_fma(A0.y, yy2, f2_fma(A1.x, zz2,
                 f2_fma(A1.y, xy2, f2_fma(A2.x, xz2, f2_fma(A2.y, yz2,
                 f2_fma(A3.x, x2,  f2_fma(A3.y, y2,  f2_fma(A4.x, z2, A4.y)))))))));
        // P(x) = a0'*n2-form + Q-form
        ull P  = f2_fma(A5.x, xx2, f2_fma(A5.y, yy2, f2_fma(A6.x, zz2,
                 f2_fma(A6.y, xy2, f2_fma(A7.x, xz2, f2_fma(A7.y, yz2,
                 f2_fma(A8.x, x2,  f2_fma(A8.y, y2,  f2_fma(A9.x, z2, A9.y)))))))));
        // L(x)
        ull L = f2_fma(A10.x, x2, f2_fma(A10.y, y2, f2_fma(A11.x, z2, A11.y)));

        float n2a, n2b; f2_unpack(n2, n2a, n2b);
        n2a = fmaxf(n2a, 0.f); n2b = fmaxf(n2b, 0.f);
        ull s2 = f2_pack(sqrt_ap(n2a), sqrt_ap(n2b));
        ull n2c = f2_pack(n2a, n2b);

        ull u  = f2_fma(n2c, NEG1, L);            // L - n2
        ull tt = f2_fma(u, s2, P);                // denom - numer
        ull denom = f2_fma(L, s2, P);

        float ta, tb; f2_unpack(tt, ta, tb);
        float da, db; f2_unpack(denom, da, db);
        float wa = fmaxf(ta, 0.f) * rcp_ap(fmaxf(da, 1e-30f));
        float wb = fmaxf(tb, 0.f) * rcp_ap(fmaxf(db, 1e-30f));
        ull w2 = f2_pack(wa, wb);

        wsum2 = f2_add(wsum2, w2);
        wt0 = f2_fma(w2, A12.x, wt0);
        wt1 = f2_fma(w2, A12.y, wt1);
        wt2 = f2_fma(w2, A13.x, wt2);

        SW[j * TPB + threadIdx.x] = w2;
    }

    // ---- Loop B: T = Sum w R ----
    ull t00 = 0ull, t01 = 0ull, t02 = 0ull;
    ull t10 = 0ull, t11 = 0ull, t12 = 0ull;
    ull t20 = 0ull, t21 = 0ull, t22 = 0ull;

#pragma unroll 8
    for (int j = 0; j < NJ; ++j) {
        const ulonglong2* C = reinterpret_cast<const ulonglong2*>(SB + j * 12);
        const ulonglong2 B0 = C[0], B1 = C[1], B2 = C[2], B3 = C[3];
        const ull R22 = SB[j * 12 + 8];
        const ull w2 = SW[j * TPB + threadIdx.x];

        t00 = f2_fma(w2, B0.x, t00);
        t01 = f2_fma(w2, B0.y, t01);
        t02 = f2_fma(w2, B1.x, t02);
        t10 = f2_fma(w2, B1.y, t10);
        t11 = f2_fma(w2, B2.x, t11);
        t12 = f2_fma(w2, B2.y, t12);
        t20 = f2_fma(w2, B3.x, t20);
        t21 = f2_fma(w2, B3.y, t21);
        t22 = f2_fma(w2, R22, t22);
    }

    // ---- epilogue per lane ----
    const float vxa = __ldg(&vdir[3 * i0]),     vxb = __ldg(&vdir[3 * i1]);
    const float vya = __ldg(&vdir[3 * i0 + 1]), vyb = __ldg(&vdir[3 * i1 + 1]);
    const float vza = __ldg(&vdir[3 * i0 + 2]), vzb = __ldg(&vdir[3 * i1 + 2]);

    float wsa, wsb; f2_unpack(wsum2, wsa, wsb);
    float w0a, w0b; f2_unpack(wt0, w0a, w0b);
    float w1a, w1b; f2_unpack(wt1, w1a, w1b);
    float w2a, w2b; f2_unpack(wt2, w2a, w2b);
    float a00, b00; f2_unpack(t00, a00, b00);
    float a01, b01; f2_unpack(t01, a01, b01);
    float a02, b02; f2_unpack(t02, a02, b02);
    float a10, b10; f2_unpack(t10, a10, b10);
    float a11, b11; f2_unpack(t11, a11, b11);
    float a12, b12; f2_unpack(t12, a12, b12);
    float a20, b20; f2_unpack(t20, a20, b20);
    float a21, b21; f2_unpack(t21, a21, b21);
    float a22, b22; f2_unpack(t22, a22, b22);

    float xa, xb, ya, yb, za, zb;
    f2_unpack(x2, xa, xb); f2_unpack(y2, ya, yb); f2_unpack(z2, za, zb);

    float* outv = out + (size_t)3 * n;

    if (wsa > EPSF) {
        float inv = rcp_ap(wsa);
        out[3 * i0]     = fmaf(a00, xa, fmaf(a01, ya, fmaf(a02, za, w0a))) * inv;
        out[3 * i0 + 1] = fmaf(a10, xa, fmaf(a11, ya, fmaf(a12, za, w1a))) * inv;
        out[3 * i0 + 2] = fmaf(a20, xa, fmaf(a21, ya, fmaf(a22, za, w2a))) * inv;
        outv[3 * i0]     = fmaf(a00, vxa, fmaf(a01, vya, a02 * vza)) * inv;
        outv[3 * i0 + 1] = fmaf(a10, vxa, fmaf(a11, vya, a12 * vza)) * inv;
        outv[3 * i0 + 2] = fmaf(a20, vxa, fmaf(a21, vya, a22 * vza)) * inv;
    } else {
        out[3 * i0] = xa;  out[3 * i0 + 1] = ya;  out[3 * i0 + 2] = za;
        outv[3 * i0] = vxa; outv[3 * i0 + 1] = vya; outv[3 * i0 + 2] = vza;
    }
    if (wsb > EPSF) {
        float inv = rcp_ap(wsb);
        out[3 * i1]     = fmaf(b00, xb, fmaf(b01, yb, fmaf(b02, zb, w0b))) * inv;
        out[3 * i1 + 1] = fmaf(b10, xb, fmaf(b11, yb, fmaf(b12, zb, w1b))) * inv;
        out[3 * i1 + 2] = fmaf(b20, xb, fmaf(b21, yb, fmaf(b22, zb, w2b))) * inv;
        outv[3 * i1]     = fmaf(b00, vxb, fmaf(b01, vyb, b02 * vzb)) * inv;
        outv[3 * i1 + 1] = fmaf(b10, vxb, fmaf(b11, vyb, b12 * vzb)) * inv;
        outv[3 * i1 + 2] = fmaf(b20, vxb, fmaf(b21, vyb, b22 * vzb)) * inv;
    } else {
        out[3 * i1] = xb;  out[3 * i1 + 1] = yb;  out[3 * i1 + 2] = zb;
        outv[3 * i1] = vxb; outv[3 * i1 + 1] = vyb; outv[3 * i1 + 2] = vzb;
    }
}

extern "C" void kernel_launch(void* const* d_in, const int* in_sizes, int n_in,
                              void* d_out, int out_size) {
    const float* xyz        = (const float*)d_in[0];
    const float* viewdirs   = (const float*)d_in[1];
    const float* transforms = (const float*)d_in[2];
    // d_in[3] = ray_valid — unused
    const float* sh_feats   = (const float*)d_in[4];
    const float* locs       = (const float*)d_in[5];
    float* out = (float*)d_out;

    int n = in_sizes[0] / 3;      // 524288
    int half = n / 2;             // 262144
    int blocks = (half + TPB - 1) / TPB;
    shCaster_kernel<<<blocks, TPB>>>(xyz, viewdirs, transforms, sh_feats,
                                     locs, out, half, n);
}

// round 13
// speedup vs baseline: 1.0849x; 1.0849x over previous
#include <cuda_runtime.h>
#include <cuda_bf16.h>

#define NJ 24
#define EPSF 1e-6f

typedef unsigned long long ull;

// ---- packed f32x2 helpers (sm_103a) ----
__device__ __forceinline__ ull f2_fma(ull a, ull b, ull c) {
    ull d; asm("fma.rn.f32x2 %0, %1, %2, %3;" : "=l"(d) : "l"(a), "l"(b), "l"(c)); return d;
}
__device__ __forceinline__ ull f2_mul(ull a, ull b) {
    ull d; asm("mul.rn.f32x2 %0, %1, %2;" : "=l"(d) : "l"(a), "l"(b)); return d;
}
__device__ __forceinline__ ull f2_add(ull a, ull b) {
    ull d; asm("add.rn.f32x2 %0, %1, %2;" : "=l"(d) : "l"(a), "l"(b)); return d;
}
__device__ __forceinline__ ull f2_pack(float lo, float hi) {
    ull d;
    asm("mov.b64 %0, {%1, %2};" : "=l"(d) : "r"(__float_as_uint(lo)), "r"(__float_as_uint(hi)));
    return d;
}
__device__ __forceinline__ void f2_unpack(ull a, float& lo, float& hi) {
    unsigned int l, h;
    asm("mov.b64 {%0, %1}, %2;" : "=r"(l), "=r"(h) : "l"(a));
    lo = __uint_as_float(l); hi = __uint_as_float(h);
}
__device__ __forceinline__ float sqrt_ap(float x) {
    float r; asm("sqrt.approx.f32 %0, %1;" : "=f"(r) : "f"(x)); return r;
}
__device__ __forceinline__ float rcp_ap(float x) {
    float r; asm("rcp.approx.f32 %0, %1;" : "=f"(r) : "f"(x)); return r;
}

// Shared layout per joint: 24 constants duplicated as {c,c} pairs (12 ulonglong2):
//  pairs 0..5 : transform rows (m00 m01 | m02 m03 | m10 m11 | m12 m13 | m20 m21 | m22 m23)
//  pair  6,7  : lx ly | lz a0'     a0' = C0*f0 + 0.5 - C2c*f6
//  pair  8,9  : a1 a2 | a3 a4      a1=-C1*f1, a2=C1*f2, a3=-C1*f3, a4=B*f4
//  pair 10,11 : a5 b6 | a7 a8      a5=-B*f5, b6=3*C2c*f6, a7=-B*f7, a8=D*f8

__global__ __launch_bounds__(256, 4)   // force <=64 regs -> 4 CTAs/SM
void shCaster_kernel(const float* __restrict__ xyz,
                     const float* __restrict__ vdir,
                     const float* __restrict__ transforms,
                     const float* __restrict__ sh_feats,
                     const float* __restrict__ locs,
                     float* __restrict__ out,
                     int half, int n)
{
    __shared__ __align__(16) ull S2[NJ * 24];

    {
        const float coef0 = 0.28209479177387814f;
        const float coefA = 0.4886025119029199f;
        const float coefB = 1.0925484305920792f;
        const float coefC = 0.31539156525252005f;
        const float coefD = 0.5462742152960396f;
        for (int idx = threadIdx.x; idx < NJ * 24; idx += blockDim.x) {
            int j = idx / 24, k = idx % 24;
            float v;
            if (k < 12) {
                v = transforms[j * 16 + k];
            } else if (k < 15) {
                v = locs[j * 3 + (k - 12)];
            } else if (k == 15) {
                v = coef0 * sh_feats[j * 9 + 0] + 0.5f - coefC * sh_feats[j * 9 + 6];
            } else if (k == 16) {
                v = -coefA * sh_feats[j * 9 + 1];
            } else if (k == 17) {
                v =  coefA * sh_feats[j * 9 + 2];
            } else if (k == 18) {
                v = -coefA * sh_feats[j * 9 + 3];
            } else if (k == 19) {
                v =  coefB * sh_feats[j * 9 + 4];
            } else if (k == 20) {
                v = -coefB * sh_feats[j * 9 + 5];
            } else if (k == 21) {
                v = 3.0f * coefC * sh_feats[j * 9 + 6];
            } else if (k == 22) {
                v = -coefB * sh_feats[j * 9 + 7];
            } else {
                v =  coefD * sh_feats[j * 9 + 8];
            }
            unsigned int b = __float_as_uint(v);
            S2[j * 24 + k] = ((ull)b << 32) | b;
        }
    }
    __syncthreads();

    int t = blockIdx.x * blockDim.x + threadIdx.x;
    if (t >= half) return;
    int i0 = t, i1 = t + half;

    const ull x2  = f2_pack(__ldg(&xyz[3 * i0]),     __ldg(&xyz[3 * i1]));
    const ull y2  = f2_pack(__ldg(&xyz[3 * i0 + 1]), __ldg(&xyz[3 * i1 + 1]));
    const ull z2  = f2_pack(__ldg(&xyz[3 * i0 + 2]), __ldg(&xyz[3 * i1 + 2]));
    const ull vx2 = f2_pack(__ldg(&vdir[3 * i0]),     __ldg(&vdir[3 * i1]));
    const ull vy2 = f2_pack(__ldg(&vdir[3 * i0 + 1]), __ldg(&vdir[3 * i1 + 1]));
    const ull vz2 = f2_pack(__ldg(&vdir[3 * i0 + 2]), __ldg(&vdir[3 * i1 + 2]));

    const ull NEG1 = f2_pack(-1.f, -1.f);

    ull wsum2 = 0ull;
    ull ox2 = 0ull, oy2 = 0ull, oz2 = 0ull;   // sum w * p
    ull rx2 = 0ull, ry2 = 0ull, rz2 = 0ull;   // sum w * (R v)

#pragma unroll
    for (int j = 0; j < NJ; ++j) {
        const ulonglong2* C = reinterpret_cast<const ulonglong2*>(S2 + j * 24);
        const ulonglong2 c0 = C[0];
        const ulonglong2 c1 = C[1];
        const ulonglong2 c2 = C[2];
        const ulonglong2 c3 = C[3];
        const ulonglong2 c4 = C[4];
        const ulonglong2 c5 = C[5];
        const ulonglong2 c6 = C[6];
        const ulonglong2 c7 = C[7];
        const ulonglong2 c8 = C[8];
        const ulonglong2 c9 = C[9];
        const ulonglong2 cA = C[10];
        const ulonglong2 cB = C[11];

        // p = (M [x,1])[:3]
        ull px = f2_fma(c0.x, x2, f2_fma(c0.y, y2, f2_fma(c1.x, z2, c1.y)));
        ull py = f2_fma(c2.x, x2, f2_fma(c2.y, y2, f2_fma(c3.x, z2, c3.y)));
        ull pz = f2_fma(c4.x, x2, f2_fma(c4.y, y2, f2_fma(c5.x, z2, c5.y)));

        // R v
        ull Rx = f2_fma(c0.x, vx2, f2_fma(c0.y, vy2, f2_mul(c1.x, vz2)));
        ull Ry = f2_fma(c2.x, vx2, f2_fma(c2.y, vy2, f2_mul(c3.x, vz2)));
        ull Rz = f2_fma(c4.x, vx2, f2_fma(c4.y, vy2, f2_mul(c5.x, vz2)));

        // d = loc - p
        ull dx = f2_fma(px, NEG1, c6.x);
        ull dy = f2_fma(py, NEG1, c6.y);
        ull dz = f2_fma(pz, NEG1, c7.x);

        ull sx = f2_mul(dx, dx);
        ull sy = f2_mul(dy, dy);
        ull sz = f2_mul(dz, dz);
        ull n2 = f2_add(f2_add(sx, sy), sz);

        // linear SH on d
        ull L = f2_fma(c8.x, dy, f2_fma(c8.y, dz, f2_mul(c9.x, dx)));

        // quadratic SH on d
        ull Q = f2_mul(c9.y, f2_mul(dx, dy));
        Q = f2_fma(cA.x, f2_mul(dy, dz), Q);
        Q = f2_fma(cA.y, sz, Q);
        Q = f2_fma(cB.x, f2_mul(dx, dz), Q);
        Q = f2_fma(cB.y, f2_fma(sy, NEG1, sx), Q);

        // s = sqrt(n2) per lane
        float n2a, n2b; f2_unpack(n2, n2a, n2b);
        ull s2 = f2_pack(sqrt_ap(n2a), sqrt_ap(n2b));

        // denom = rad*n2 = a0'*n2 + L*s + Q ; numer = n2*s
        ull denom = f2_fma(c7.y, n2, Q);
        denom = f2_fma(L, s2, denom);
        ull tt = f2_fma(f2_mul(n2, s2), NEG1, denom);   // denom - numer

        // w = relu(denom-numer)/denom  (zero whenever rad <= 0)
        float ta, tb; f2_unpack(tt, ta, tb);
        float da, db; f2_unpack(denom, da, db);
        float wa = fmaxf(ta, 0.f) * rcp_ap(fmaxf(da, 1e-30f));
        float wb = fmaxf(tb, 0.f) * rcp_ap(fmaxf(db, 1e-30f));
        ull w2 = f2_pack(wa, wb);

        wsum2 = f2_add(wsum2, w2);
        ox2 = f2_fma(w2, px, ox2);
        oy2 = f2_fma(w2, py, oy2);
        oz2 = f2_fma(w2, pz, oz2);
        rx2 = f2_fma(w2, Rx, rx2);
        ry2 = f2_fma(w2, Ry, ry2);
        rz2 = f2_fma(w2, Rz, rz2);
    }

    // ---- epilogue per lane ----
    float wsa, wsb;  f2_unpack(wsum2, wsa, wsb);
    float oxa, oxb;  f2_unpack(ox2, oxa, oxb);
    float oya, oyb;  f2_unpack(oy2, oya, oyb);
    float oza, ozb;  f2_unpack(oz2, oza, ozb);
    float rxa, rxb;  f2_unpack(rx2, rxa, rxb);
    float rya, ryb;  f2_unpack(ry2, rya, ryb);
    float rza, rzb;  f2_unpack(rz2, rza, rzb);

    float xa, xb, ya, yb, za, zb, vxa, vxb, vya, vyb, vza, vzb;
    f2_unpack(x2, xa, xb);   f2_unpack(y2, ya, yb);   f2_unpack(z2, za, zb);
    f2_unpack(vx2, vxa, vxb); f2_unpack(vy2, vya, vyb); f2_unpack(vz2, vza, vzb);

    float* outv = out + (size_t)3 * n;

    if (wsa > EPSF) {
        float inv = rcp_ap(wsa);
        out[3 * i0] = oxa * inv;  out[3 * i0 + 1] = oya * inv;  out[3 * i0 + 2] = oza * inv;
        outv[3 * i0] = rxa * inv; outv[3 * i0 + 1] = rya * inv; outv[3 * i0 + 2] = rza * inv;
    } else {
        out[3 * i0] = xa;  out[3 * i0 + 1] = ya;  out[3 * i0 + 2] = za;
        outv[3 * i0] = vxa; outv[3 * i0 + 1] = vya; outv[3 * i0 + 2] = vza;
    }
    if (wsb > EPSF) {
        float inv = rcp_ap(wsb);
        out[3 * i1] = oxb * inv;  out[3 * i1 + 1] = oyb * inv;  out[3 * i1 + 2] = ozb * inv;
        outv[3 * i1] = rxb * inv; outv[3 * i1 + 1] = ryb * inv; outv[3 * i1 + 2] = rzb * inv;
    } else {
        out[3 * i1] = xb;  out[3 * i1 + 1] = yb;  out[3 * i1 + 2] = zb;
        outv[3 * i1] = vxb; outv[3 * i1 + 1] = vyb; outv[3 * i1 + 2] = vzb;
    }
}

extern "C" void kernel_launch(void* const* d_in, const int* in_sizes, int n_in,
                              void* d_out, int out_size) {
    const float* xyz        = (const float*)d_in[0];
    const float* viewdirs   = (const float*)d_in[1];
    const float* transforms = (const float*)d_in[2];
    // d_in[3] = ray_valid — unused
    const float* sh_feats   = (const float*)d_in[4];
    const float* locs       = (const float*)d_in[5];
    float* out = (float*)d_out;

    int n = in_sizes[0] / 3;      // 524288
    int half = n / 2;             // 262144
    int threads = 256;
    int blocks = (half + threads - 1) / threads;
    shCaster_kernel<<<blocks, threads>>>(xyz, viewdirs, transforms, sh_feats,
                                         locs, out, half, n);
}